// round 4
// baseline (speedup 1.0000x reference)
#include <cuda_runtime.h>
#include <cstdint>

// Holonomy: out[b,l] = M_15 @ ... @ M_1 @ M_0,  M_t = Gamma[b, loops[l][t+1], loops[l][t]]
// Gamma: [4, 512, 512, 8, 8] fp32; loops: [64, 17] integer; out: [4, 64, 8, 8] fp32.
//
// One block per (b, l) chain. 64 threads = one per output element.
// loops dtype (int32 vs int64) is detected on-device: for int64 data with
// values < 2^31, every odd 32-bit word is 0; for int32 random data in [0,512)
// the chance all 64 checked odd words are zero is ~512^-64.

#define BATCH   4
#define SEQ     512
#define KDIM    8
#define NLOOPS  64
#define LOOPLEN 17
#define NSTEPS  (LOOPLEN - 1)   // 16

__global__ void __launch_bounds__(64, 4) holonomy_kernel(
    const float* __restrict__ Gamma,
    const int*   __restrict__ loops_w,   // raw 32-bit view of loops buffer
    float* __restrict__ out)
{
    const int bl  = blockIdx.x;        // b*NLOOPS + l
    const int b   = bl >> 6;
    const int l   = bl & 63;
    const int tid = threadIdx.x;       // 0..63
    const int ty  = tid >> 3;          // row i
    const int tx  = tid & 7;           // col j

    __shared__ float Ms[NSTEPS][64];
    __shared__ float holA[64];
    __shared__ float holB[64];
    __shared__ int   idx[LOOPLEN];
    __shared__ int   not64;

    // --- dtype detection: check odd 32-bit words 1,3,...,127 (safe for both dtypes)
    if (tid == 0) not64 = 0;
    __syncthreads();
    if (loops_w[2 * tid + 1] != 0) atomicOr(&not64, 1);
    __syncthreads();
    const bool is64 = (not64 == 0);

    if (tid < LOOPLEN) {
        const int e = l * LOOPLEN + tid;
        int v = is64 ? loops_w[2 * e] : loops_w[e];
        idx[tid] = v & (SEQ - 1);      // defensive: never OOB
    }
    __syncthreads();

    // Issue all 16 gathers back-to-back: each is one coalesced 256B row.
    const float* Gb = Gamma + (size_t)b * SEQ * SEQ * (KDIM * KDIM);
    #pragma unroll
    for (int t = 0; t < NSTEPS; t++) {
        const int ii = idx[t + 1];
        const int jj = idx[t];
        Ms[t][tid] = Gb[((size_t)ii * SEQ + jj) * (KDIM * KDIM) + tid];
    }

    // hol = M_0 (identity init folded away). Same-thread write/read needs no sync;
    // the syncthreads below publishes everything for the chain.
    holA[tid] = Ms[0][tid];
    __syncthreads();

    // Chain: hol_new[i][j] = sum_k M_t[i][k] * hol[k][j]
    #pragma unroll
    for (int t = 1; t < NSTEPS; t++) {
        const float* __restrict__ src = (t & 1) ? holA : holB;
        float*       __restrict__ dst = (t & 1) ? holB : holA;
        float c = 0.f;
        #pragma unroll
        for (int k = 0; k < KDIM; k++)
            c = fmaf(Ms[t][ty * KDIM + k], src[k * KDIM + tx], c);
        dst[tid] = c;
        __syncthreads();
    }

    // Last write (t = 15, odd) went to holB.
    out[(size_t)bl * 64 + tid] = holB[tid];
}

extern "C" void kernel_launch(void* const* d_in, const int* in_sizes, int n_in,
                              void* d_out, int out_size)
{
    // Defensive input-order resolution via element counts:
    // Gamma = 4*512*512*64 = 67,108,864 elems; loops = 64*17 = 1088 elems.
    int gi = 0, li = 1;
    if (n_in >= 2 && in_sizes[0] < in_sizes[1]) { gi = 1; li = 0; }

    const float* Gamma   = (const float*)d_in[gi];
    const int*   loops_w = (const int*)d_in[li];
    float*       out     = (float*)d_out;

    holonomy_kernel<<<BATCH * NLOOPS, 64>>>(Gamma, loops_w, out);
}

// round 8
// speedup vs baseline: 1.2546x; 1.2546x over previous
#include <cuda_runtime.h>
#include <cstdint>

// Holonomy: out[b,l] = M_15 @ ... @ M_1 @ M_0,  M_t = Gamma[b, loops[l][t+1], loops[l][t]]
// Gamma: [4, 512, 512, 8, 8] fp32; loops: [64, 17] int (32 or 64 bit); out: [4,64,8,8] fp32.
//
// One WARP per chain; fully warp-synchronous (no smem, no __syncthreads).
// Lane r*8+c (r=0..3, c=0..7) holds elements (r,c) and (r+4,c) of each matrix.
// All 16 gathered matrices live in registers; the sequential product runs on
// registers + shuffles with two independent accumulator chains.
//
// loops dtype detected per-warp: int64 data (values < 2^31) has every odd
// 32-bit word zero; 32 sampled odd words being all-zero under int32 random
// data in [0,512) has probability 512^-32.

#define BATCH   4
#define SEQ     512
#define NLOOPS  64
#define LOOPLEN 17
#define NSTEPS  (LOOPLEN - 1)   // 16
#define NCHAINS (BATCH * NLOOPS) // 256
#define WARPS_PER_BLOCK 4

__global__ void __launch_bounds__(32 * WARPS_PER_BLOCK, 8) holonomy_kernel(
    const float* __restrict__ Gamma,
    const int*   __restrict__ loops_w,   // raw 32-bit view of loops buffer
    float* __restrict__ out)
{
    const int lane = threadIdx.x & 31;
    const int w    = blockIdx.x * WARPS_PER_BLOCK + (threadIdx.x >> 5); // chain 0..255
    const int b    = w >> 6;
    const int r    = lane >> 3;        // 0..3
    const int c    = lane & 7;         // 0..7

    // ---- issue ALL front-end loads concurrently (one memory round trip) ----
    const int det = loops_w[2 * lane + 1];            // words 1..63: in-bounds for both dtypes
    const int l   = w & (NLOOPS - 1);
    const int e   = l * LOOPLEN + (lane < LOOPLEN ? lane : LOOPLEN - 1);
    const int c32 = loops_w[e];                       // int32 interpretation
    const int c64 = loops_w[2 * e];                   // int64 (low word) interpretation

    const unsigned nz = __ballot_sync(0xffffffffu, det != 0);
    const int v = ((nz == 0u) ? c64 : c32) & (SEQ - 1);   // defensive mask: never OOB

    // distribute loop indices to all lanes
    int idx[LOOPLEN];
    #pragma unroll
    for (int t = 0; t < LOOPLEN; t++)
        idx[t] = __shfl_sync(0xffffffffu, v, t);

    // ---- gather all 16 matrices into registers (32 coalesced LDG, MLP=32) ----
    const float* Gb = Gamma + (size_t)b * (SEQ * SEQ * 64);
    float Ma0[NSTEPS], Ma1[NSTEPS];
    #pragma unroll
    for (int t = 0; t < NSTEPS; t++) {
        const float* p = Gb + ((size_t)idx[t + 1] * SEQ + idx[t]) * 64;
        Ma0[t] = p[lane];        // element (r,   c)
        Ma1[t] = p[32 + lane];   // element (r+4, c)
    }

    // ---- register/shuffle chain: hol = M_t @ hol ----
    float h0 = Ma0[0], h1 = Ma1[0];        // init hol = M_0 (identity folded)
    #pragma unroll
    for (int t = 1; t < NSTEPS; t++) {
        float n0 = 0.f, n1 = 0.f;
        #pragma unroll
        for (int k = 0; k < 8; k++) {
            // M_t[r][k]   -> lane r*8+k, reg Ma0[t]
            // M_t[r+4][k] -> lane r*8+k, reg Ma1[t]
            // hol[k][c]   -> lane (k&3)*8+c, reg h0 (k<4) / h1 (k>=4)
            const float a0 = __shfl_sync(0xffffffffu, Ma0[t], r * 8 + k);
            const float a1 = __shfl_sync(0xffffffffu, Ma1[t], r * 8 + k);
            const float hk = __shfl_sync(0xffffffffu, (k < 4) ? h0 : h1,
                                         (k & 3) * 8 + c);
            n0 = fmaf(a0, hk, n0);
            n1 = fmaf(a1, hk, n1);
        }
        h0 = n0; h1 = n1;
    }

    float* o = out + (size_t)w * 64;
    o[lane]      = h0;
    o[32 + lane] = h1;
}

extern "C" void kernel_launch(void* const* d_in, const int* in_sizes, int n_in,
                              void* d_out, int out_size)
{
    // Defensive input-order resolution via element counts:
    // Gamma = 67,108,864 elems; loops = 1088 elems.
    int gi = 0, li = 1;
    if (n_in >= 2 && in_sizes[0] < in_sizes[1]) { gi = 1; li = 0; }

    const float* Gamma   = (const float*)d_in[gi];
    const int*   loops_w = (const int*)d_in[li];
    float*       out     = (float*)d_out;

    holonomy_kernel<<<NCHAINS / WARPS_PER_BLOCK, 32 * WARPS_PER_BLOCK>>>(Gamma, loops_w, out);
}